// round 1
// baseline (speedup 1.0000x reference)
#include <cuda_runtime.h>
#include <cstdint>

// 3x3 conv, stride 1, pad 1.
// x: [256, 512, 512] f32, W: [3,3,256,256] HWIO f32, b: [256] f32
// out: [256, 512, 512] f32
//
// Direct conv, register-tiled, f32x2 (FFMA2) accumulation over cout pairs.

#define C_IN  256
#define C_OUT 256
#define HH    512
#define WW    512
#define HWSZ  (HH * WW)

#define CI_T  8      // c_in per smem chunk
#define CO_T  64     // c_out per block
#define TH    8      // output rows per block
#define TW    16     // output cols per block

typedef unsigned long long u64;

__device__ __forceinline__ u64 pack2(float lo, float hi) {
    u64 r;
    asm("mov.b64 %0, {%1, %2};" : "=l"(r) : "f"(lo), "f"(hi));
    return r;
}
__device__ __forceinline__ void unpack2(u64 v, float& lo, float& hi) {
    asm("mov.b64 {%0, %1}, %2;" : "=f"(lo), "=f"(hi) : "l"(v));
}
__device__ __forceinline__ void fma2(u64& d, u64 a, u64 b) {
    // d = a * b + d, elementwise on packed f32x2 (sm_100+ FFMA2)
    asm("fma.rn.f32x2 %0, %1, %2, %0;" : "+l"(d) : "l"(a), "l"(b));
}

__global__ void __launch_bounds__(256)
conv3x3_kernel(const float* __restrict__ x,
               const float* __restrict__ w,
               const float* __restrict__ bias,
               float* __restrict__ out) {
    __shared__ float s_x[CI_T][TH + 2][TW + 2];   // 8 * 10 * 18 floats
    __shared__ float s_w[9][CI_T][CO_T];          // [kh*3+kw][ci][co]

    const int t      = threadIdx.x;         // 0..255
    const int co_sub = t & 15;              // 0..15  -> couts co_sub*4 .. +3
    const int pg     = t >> 4;              // 0..15
    const int row    = pg & 7;              // output row within tile
    const int colb   = (pg >> 3) * 8;       // 0 or 8: 8 consecutive output cols

    const int w0  = blockIdx.x * TW;
    const int h0  = blockIdx.y * TH;
    const int co0 = blockIdx.z * CO_T;

    // acc[pair][j]: pair 0 -> couts co_sub*4 + {0,1}; pair 1 -> + {2,3}
    u64 acc[2][8];
#pragma unroll
    for (int p = 0; p < 2; p++)
#pragma unroll
        for (int j = 0; j < 8; j++)
            acc[p][j] = pack2(0.f, 0.f);

    for (int ci0 = 0; ci0 < C_IN; ci0 += CI_T) {
        // ---- load input tile (with zero padding at image borders) ----
        const int XN = CI_T * (TH + 2) * (TW + 2);   // 1440
        for (int idx = t; idx < XN; idx += 256) {
            int ci  = idx / ((TH + 2) * (TW + 2));
            int rem = idx % ((TH + 2) * (TW + 2));
            int lh  = rem / (TW + 2);
            int lw  = rem % (TW + 2);
            int gh  = h0 + lh - 1;
            int gw  = w0 + lw - 1;
            float v = 0.f;
            if ((unsigned)gh < HH && (unsigned)gw < WW)
                v = x[(size_t)(ci0 + ci) * HWSZ + (size_t)gh * WW + gw];
            s_x[ci][lh][lw] = v;
        }
        // ---- load weight tile: W[kh][kw][ci][co], co contiguous ----
        const int WN = 9 * CI_T * CO_T;              // 4608
        for (int idx = t; idx < WN; idx += 256) {
            int k   = idx / (CI_T * CO_T);
            int rem = idx % (CI_T * CO_T);
            int ci  = rem / CO_T;
            int co  = rem % CO_T;
            s_w[k][ci][co] =
                w[((size_t)k * C_IN + (ci0 + ci)) * C_OUT + co0 + co];
        }
        __syncthreads();

        // ---- compute ----
#pragma unroll
        for (int ci = 0; ci < CI_T; ci++) {
#pragma unroll
            for (int kh = 0; kh < 3; kh++) {
                // sliding window: 10 input values cover 8 outputs x 3 taps
                u64 x2[10];
#pragma unroll
                for (int i = 0; i < 10; i++) {
                    float v = s_x[ci][row + kh][colb + i];
                    x2[i] = pack2(v, v);
                }
#pragma unroll
                for (int kw = 0; kw < 3; kw++) {
                    const u64* wp = reinterpret_cast<const u64*>(
                        &s_w[kh * 3 + kw][ci][co_sub * 4]);
                    u64 w01 = wp[0];
                    u64 w23 = wp[1];
#pragma unroll
                    for (int j = 0; j < 8; j++) {
                        fma2(acc[0][j], w01, x2[j + kw]);
                        fma2(acc[1][j], w23, x2[j + kw]);
                    }
                }
            }
        }
        __syncthreads();
    }

    // ---- bias + store ----
    float r0[8], r1[8], r2[8], r3[8];
#pragma unroll
    for (int j = 0; j < 8; j++) {
        unpack2(acc[0][j], r0[j], r1[j]);
        unpack2(acc[1][j], r2[j], r3[j]);
    }
    const int co_base = co0 + co_sub * 4;
    const float b0 = bias[co_base + 0];
    const float b1 = bias[co_base + 1];
    const float b2 = bias[co_base + 2];
    const float b3 = bias[co_base + 3];

    const size_t pix = (size_t)(h0 + row) * WW + (w0 + colb);

#define STORE_ROW(arr, r, bb)                                                  \
    do {                                                                       \
        float4* dst = reinterpret_cast<float4*>(                               \
            out + (size_t)(co_base + (r)) * HWSZ + pix);                       \
        float4 v0 = make_float4(arr[0] + (bb), arr[1] + (bb),                  \
                                arr[2] + (bb), arr[3] + (bb));                 \
        float4 v1 = make_float4(arr[4] + (bb), arr[5] + (bb),                  \
                                arr[6] + (bb), arr[7] + (bb));                 \
        dst[0] = v0;                                                           \
        dst[1] = v1;                                                           \
    } while (0)

    STORE_ROW(r0, 0, b0);
    STORE_ROW(r1, 1, b1);
    STORE_ROW(r2, 2, b2);
    STORE_ROW(r3, 3, b3);
#undef STORE_ROW
}

extern "C" void kernel_launch(void* const* d_in, const int* in_sizes, int n_in,
                              void* d_out, int out_size) {
    const float* x = (const float*)d_in[0];   // [256,512,512]
    const float* w = (const float*)d_in[1];   // [3,3,256,256]
    const float* b = (const float*)d_in[2];   // [256]
    float* out = (float*)d_out;               // [256,512,512]

    dim3 grid(WW / TW, HH / TH, C_OUT / CO_T);  // (32, 64, 4)
    conv3x3_kernel<<<grid, 256>>>(x, w, b, out);
}

// round 3
// speedup vs baseline: 2.6882x; 2.6882x over previous
#include <cuda_runtime.h>
#include <cstdint>

// 3x3 conv s1 p1 as implicit GEMM via mma.sync m16n8k8 tf32 (sm_80 PTX,
// runs on Blackwell fallback HMMA — tcgen05 PTX is rejected at the harness's
// .target sm_103).
// x:[256,512,512] f32, W:[3,3,256,256] HWIO, b:[256], out:[256,512,512].
// CTA: 128 pixels x 128 couts. K = 2304 = 72 chunks of (kh,kw,ci0+32).

#define HH 512
#define WW 512
#define HWSZ (512*512)
#define C_OUT 256
#define NCHUNK 72
#define KSTRIDE 136                      // floats per k-row (pad: bank = 8*tig+gid, conflict-free)
#define TILE_FLOATS (32 * KSTRIDE)       // 4352 floats = 17408 B (one of A or B)
#define STAGE_FLOATS (2 * TILE_FLOATS)   // A + B
#define SMEM_BYTES (2 * STAGE_FLOATS * 4)

__device__ __forceinline__ uint32_t to_tf32(float f) {
    uint32_t r;
    asm("cvt.rna.tf32.f32 %0, %1;" : "=r"(r) : "f"(f));
    return r;
}
__device__ __forceinline__ void cp_async4(uint32_t dst, const void* src, uint32_t sz) {
    asm volatile("cp.async.ca.shared.global [%0], [%1], 4, %2;"
                 :: "r"(dst), "l"(src), "r"(sz) : "memory");
}
__device__ __forceinline__ void cp_async16(uint32_t dst, const void* src) {
    asm volatile("cp.async.cg.shared.global [%0], [%1], 16;"
                 :: "r"(dst), "l"(src) : "memory");
}
__device__ __forceinline__ void cp_commit() {
    asm volatile("cp.async.commit_group;" ::: "memory");
}
__device__ __forceinline__ void cp_wait1() {
    asm volatile("cp.async.wait_group 1;" ::: "memory");
}
__device__ __forceinline__ void mma_tf32(float* c, const uint32_t* a, const uint32_t* b) {
    asm volatile(
        "mma.sync.aligned.m16n8k8.row.col.f32.tf32.tf32.f32 "
        "{%0,%1,%2,%3}, {%4,%5,%6,%7}, {%8,%9}, {%0,%1,%2,%3};"
        : "+f"(c[0]), "+f"(c[1]), "+f"(c[2]), "+f"(c[3])
        : "r"(a[0]), "r"(a[1]), "r"(a[2]), "r"(a[3]), "r"(b[0]), "r"(b[1]));
}

__global__ void __launch_bounds__(256, 2)
conv_mma(const float* __restrict__ x, const float* __restrict__ w,
         const float* __restrict__ bias, float* __restrict__ out)
{
    extern __shared__ float dsm[];

    const int tid  = threadIdx.x;
    const int wid  = tid >> 5;
    const int lane = tid & 31;
    const int gid  = lane >> 2;     // 0..7
    const int tig  = lane & 3;      // 0..3
    const int wm   = wid & 3;       // warp m-offset: 32*wm
    const int wn   = wid >> 2;      // warp n-offset: 64*wn

    const int w0  = blockIdx.x * 128;
    const int h   = blockIdx.y;
    const int co0 = blockIdx.z * 128;

    const uint32_t sbase = (uint32_t)__cvta_generic_to_shared(dsm);

    float acc[2][8][4];
#pragma unroll
    for (int mt = 0; mt < 2; mt++)
#pragma unroll
        for (int nt = 0; nt < 8; nt++)
#pragma unroll
            for (int i = 0; i < 4; i++)
                acc[mt][nt][i] = 0.f;

    // ---- producer: fill stage with chunk c ----
    auto load_chunk = [&](int c, int stage) {
        const int kh  = c / 24;
        const int r   = c % 24;
        const int kw  = r >> 3;
        const int ci0 = (r & 7) * 32;

        const uint32_t abase = sbase + (uint32_t)stage * (STAGE_FLOATS * 4);
        const uint32_t bbase = abase + TILE_FLOATS * 4;

        const int h2  = h + kh - 1;
        const bool hok = (unsigned)h2 < (unsigned)HH;
        const float* xrow = x + (size_t)ci0 * HWSZ + (size_t)(hok ? h2 : 0) * WW;

        // A: im2col tile [k=32][m=128], 4096 scalars, 16 per thread
#pragma unroll
        for (int i = 0; i < 16; i++) {
            const int j = tid + i * 256;
            const int k = j >> 7, m = j & 127;
            const int w2 = w0 + m + kw - 1;
            const bool ok = hok && ((unsigned)w2 < (unsigned)WW);
            const float* src = xrow + (size_t)k * HWSZ + (ok ? w2 : 0);
            cp_async4(abase + (uint32_t)(k * KSTRIDE + m) * 4u, src, ok ? 4u : 0u);
        }
        // B: W[kh][kw][ci0+k][co0..+128], [k=32][n=128], float4 x 4 per thread
        const float* wb = w + ((size_t)(kh * 3 + kw) * 256 + ci0) * C_OUT + co0;
#pragma unroll
        for (int i = 0; i < 4; i++) {
            const int j = tid + i * 256;
            const int k = j >> 5, q = (j & 31) * 4;
            cp_async16(bbase + (uint32_t)(k * KSTRIDE + q) * 4u,
                       wb + (size_t)k * C_OUT + q);
        }
    };

    load_chunk(0, 0); cp_commit();
    load_chunk(1, 1); cp_commit();

    for (int c = 0; c < NCHUNK; c++) {
        cp_wait1();
        __syncthreads();

        const float* As = dsm + (c & 1) * STAGE_FLOATS;
        const float* Bs = As + TILE_FLOATS;

#pragma unroll
        for (int ks = 0; ks < 4; ks++) {
            const int kb = ks * 8 + tig;     // frag k-col for a0/a1, b0; +4 for others
            uint32_t afrag[2][4];
#pragma unroll
            for (int mt = 0; mt < 2; mt++) {
                const int m = wm * 32 + mt * 16 + gid;
                afrag[mt][0] = to_tf32(As[kb * KSTRIDE + m]);
                afrag[mt][1] = to_tf32(As[kb * KSTRIDE + m + 8]);
                afrag[mt][2] = to_tf32(As[(kb + 4) * KSTRIDE + m]);
                afrag[mt][3] = to_tf32(As[(kb + 4) * KSTRIDE + m + 8]);
            }
            uint32_t bfrag[8][2];
#pragma unroll
            for (int nt = 0; nt < 8; nt++) {
                const int n = wn * 64 + nt * 8 + gid;
                bfrag[nt][0] = to_tf32(Bs[kb * KSTRIDE + n]);
                bfrag[nt][1] = to_tf32(Bs[(kb + 4) * KSTRIDE + n]);
            }
#pragma unroll
            for (int mt = 0; mt < 2; mt++)
#pragma unroll
                for (int nt = 0; nt < 8; nt++)
                    mma_tf32(acc[mt][nt], afrag[mt], bfrag[nt]);
        }

        __syncthreads();
        if (c + 2 < NCHUNK) load_chunk(c + 2, c & 1);
        cp_commit();
    }

    // ---- epilogue: bias + store ----
    const size_t prow = (size_t)h * WW + w0;
#pragma unroll
    for (int nt = 0; nt < 8; nt++) {
        const int co = co0 + wn * 64 + nt * 8 + tig * 2;
        const float b0 = __ldg(bias + co);
        const float b1 = __ldg(bias + co + 1);
        float* o0 = out + (size_t)co * HWSZ + prow;
        float* o1 = o0 + HWSZ;
#pragma unroll
        for (int mt = 0; mt < 2; mt++) {
            const int m = wm * 32 + mt * 16 + gid;
            o0[m]     = acc[mt][nt][0] + b0;
            o1[m]     = acc[mt][nt][1] + b1;
            o0[m + 8] = acc[mt][nt][2] + b0;
            o1[m + 8] = acc[mt][nt][3] + b1;
        }
    }
}

extern "C" void kernel_launch(void* const* d_in, const int* in_sizes, int n_in,
                              void* d_out, int out_size) {
    const float* x = (const float*)d_in[0];   // [256,512,512]
    const float* w = (const float*)d_in[1];   // [3,3,256,256]
    const float* b = (const float*)d_in[2];   // [256]
    float* out = (float*)d_out;               // [256,512,512]

    cudaFuncSetAttribute(conv_mma, cudaFuncAttributeMaxDynamicSharedMemorySize, SMEM_BYTES);
    dim3 grid(4, HH, 2);   // 4 w-tiles x 512 rows x 2 cout halves
    conv_mma<<<grid, 256, SMEM_BYTES>>>(x, w, b, out);
}